// round 1
// baseline (speedup 1.0000x reference)
#include <cuda_runtime.h>
#include <cuda_bf16.h>

// Problem constants
#define BB   256
#define TT   512
#define IND  128
#define HID  100
#define G4   400          // 4*HID
#define MTOT (BB*TT)      // 131072

// ---------------- device scratch (static globals; no runtime alloc) -------------
__device__ float g_xT[IND * MTOT];      // [k][m]  transposed input (67 MB)
__device__ float g_WihT[IND * G4];      // [k][g]
__device__ float g_bias[G4];            // bih + bhh
__device__ float g_pre[MTOT * G4];      // [m][g]  input projection (210 MB)
__device__ float g_hfinal[BB * HID];    // layer-0 final hidden state

// ---------------- f32x2 packed helpers (Blackwell) ------------------------------
__device__ __forceinline__ unsigned long long fma2(unsigned long long a,
                                                   unsigned long long b,
                                                   unsigned long long c) {
    unsigned long long d;
    asm("fma.rn.f32x2 %0, %1, %2, %3;" : "=l"(d) : "l"(a), "l"(b), "l"(c));
    return d;
}
__device__ __forceinline__ unsigned long long pack2(float lo, float hi) {
    unsigned long long d;
    asm("mov.b64 %0, {%1, %2};" : "=l"(d) : "f"(lo), "f"(hi));
    return d;
}
__device__ __forceinline__ float2 unpack2(unsigned long long v) {
    float lo, hi;
    asm("mov.b64 {%0, %1}, %2;" : "=f"(lo), "=f"(hi) : "l"(v));
    return make_float2(lo, hi);
}

// ---------------- accurate-enough fast activations -------------------------------
// sigmoid via exp(-|x|) so the division operand stays in [1,2] (safe for fdividef)
__device__ __forceinline__ float sigf(float x) {
    float e = __expf(-fabsf(x));            // (0,1]
    float r = __fdividef(1.f, 1.f + e);     // sigma(|x|)
    return (x >= 0.f) ? r : 1.f - r;
}
__device__ __forceinline__ float tanhf_(float x) {
    float e = __expf(-2.f * fabsf(x));      // (0,1]
    float r = __fdividef(1.f - e, 1.f + e); // tanh(|x|)
    return (x >= 0.f) ? r : -r;
}

// ================= K-prep: WihT + fused bias =====================================
__global__ void prep_kernel(const float* __restrict__ Wih,
                            const float* __restrict__ bih,
                            const float* __restrict__ bhh) {
    int idx = blockIdx.x * 256 + threadIdx.x;
    if (idx < G4 * IND) {
        int g = idx / IND, k = idx - g * IND;
        g_WihT[k * G4 + g] = Wih[idx];
    }
    if (idx < G4) g_bias[idx] = bih[idx] + bhh[idx];
}

// ================= K0: transpose x [M,128] -> xT [128,M] =========================
__global__ void transpose_x_kernel(const float* __restrict__ x) {
    __shared__ float tile[32][33];
    int m0 = blockIdx.x * 32;
    int k0 = blockIdx.y * 32;
    int tx = threadIdx.x, ty = threadIdx.y;     // block (32,8)
#pragma unroll
    for (int j = 0; j < 32; j += 8)
        tile[ty + j][tx] = x[(m0 + ty + j) * IND + k0 + tx];
    __syncthreads();
#pragma unroll
    for (int j = 0; j < 32; j += 8)
        g_xT[(k0 + ty + j) * MTOT + m0 + tx] = tile[tx][ty + j];
}

// ================= K1: pre = x @ WihT + bias  (f32x2 GEMM) =======================
// Block tile 64 rows x 100 gates, K staged in two 64-halves (static smem < 48KB).
// thread (ty = tid&15 -> 4 rows, tx = tid>>4 < 25 -> 4 gates), 16 accumulators
// as 8 packed f32x2 (lane pair = adjacent gates).
__global__ void __launch_bounds__(416, 2) gemm_pre_kernel() {
    __shared__ float xs[64 * 68];    // [k][row], padded to 68 (16B-aligned rows)
    __shared__ float ws[64 * 108];   // [k][gate], padded to 108

    int tid = threadIdx.x;
    int m0 = blockIdx.x * 64;
    int g0 = blockIdx.y * 100;
    int ty = tid & 15;
    int tx = tid >> 4;

    unsigned long long acc[4][2];
#pragma unroll
    for (int r = 0; r < 4; r++) { acc[r][0] = 0ULL; acc[r][1] = 0ULL; }

    for (int kk = 0; kk < IND; kk += 64) {
        __syncthreads();
        // stage x tile (64k x 64m) : coalesced from pre-transposed global
        for (int idx = tid; idx < 64 * 16; idx += 416) {
            int k = idx >> 4, i4 = idx & 15;
            float4 v = *(const float4*)&g_xT[(kk + k) * MTOT + m0 + 4 * i4];
            *(float4*)&xs[k * 68 + 4 * i4] = v;
        }
        // stage W tile (64k x 100g)
        for (int idx = tid; idx < 64 * 25; idx += 416) {
            int k = idx / 25, g4i = idx - 25 * k;
            float4 v = *(const float4*)&g_WihT[(kk + k) * G4 + g0 + 4 * g4i];
            *(float4*)&ws[k * 108 + 4 * g4i] = v;
        }
        __syncthreads();

        if (tx < 25) {
#pragma unroll 16
            for (int k = 0; k < 64; k++) {
                float4 xv = *(const float4*)&xs[k * 68 + 4 * ty];
                ulonglong2 wv = *(const ulonglong2*)&ws[k * 108 + 4 * tx];
                unsigned long long d0 = pack2(xv.x, xv.x);
                unsigned long long d1 = pack2(xv.y, xv.y);
                unsigned long long d2 = pack2(xv.z, xv.z);
                unsigned long long d3 = pack2(xv.w, xv.w);
                acc[0][0] = fma2(d0, wv.x, acc[0][0]);
                acc[0][1] = fma2(d0, wv.y, acc[0][1]);
                acc[1][0] = fma2(d1, wv.x, acc[1][0]);
                acc[1][1] = fma2(d1, wv.y, acc[1][1]);
                acc[2][0] = fma2(d2, wv.x, acc[2][0]);
                acc[2][1] = fma2(d2, wv.y, acc[2][1]);
                acc[3][0] = fma2(d3, wv.x, acc[3][0]);
                acc[3][1] = fma2(d3, wv.y, acc[3][1]);
            }
        }
    }

    if (tx < 25) {
        float b0 = g_bias[g0 + 4 * tx + 0];
        float b1 = g_bias[g0 + 4 * tx + 1];
        float b2 = g_bias[g0 + 4 * tx + 2];
        float b3 = g_bias[g0 + 4 * tx + 3];
#pragma unroll
        for (int r = 0; r < 4; r++) {
            float2 e0 = unpack2(acc[r][0]);
            float2 e1 = unpack2(acc[r][1]);
            float4 o = make_float4(e0.x + b0, e0.y + b1, e1.x + b2, e1.y + b3);
            *(float4*)&g_pre[(m0 + 4 * ty + r) * G4 + g0 + 4 * tx] = o;
        }
    }
}

// ================= K2: LSTM layer-0 recurrence ===================================
// 128 blocks, each owns 2 batch rows for all 512 steps (rows independent -> no
// cross-block sync). Whh row (100 floats) lives in 50 packed f32x2 registers per
// gate thread; h is broadcast from smem via 128-bit loads (lane pair = even/odd k).
__global__ void __launch_bounds__(416, 1) lstm_kernel(const float* __restrict__ Whh) {
    __shared__ float h_sh[2][112];     // row stride 112 floats = 448B (16B mult)
    __shared__ float gact[2][G4];      // activated gate values

    int tid = threadIdx.x;
    int bid = blockIdx.x;
    int r0 = bid * 2;
    int g = tid;

    unsigned long long Wp[50];
    if (tid < G4) {
#pragma unroll
        for (int j = 0; j < 50; j++)
            Wp[j] = pack2(Whh[g * HID + 2 * j], Whh[g * HID + 2 * j + 1]);
    }
    if (tid < 112) { h_sh[0][tid] = 0.f; h_sh[1][tid] = 0.f; }

    // phase-2 state: thread tid<200 owns (row r = tid/100, unit j = tid%100)
    float c = 0.f, hloc = 0.f;
    int pr = tid / 100;
    int pj = tid - pr * 100;

    const float* pre0 = g_pre + (r0 * TT) * G4 + g;
    const float* pre1 = pre0 + TT * G4;
    bool is_tanh_gate = (g >= 200 && g < 300);

    __syncthreads();

    for (int t = 0; t < TT; t++) {
        if (tid < G4) {
            float p0 = __ldg(pre0);
            float p1 = __ldg(pre1);
            unsigned long long a0 = 0ULL, a1 = 0ULL;
            const ulonglong2* h0p = (const ulonglong2*)&h_sh[0][0];
            const ulonglong2* h1p = (const ulonglong2*)&h_sh[1][0];
#pragma unroll
            for (int j = 0; j < 25; j++) {
                ulonglong2 hv0 = h0p[j];
                ulonglong2 hv1 = h1p[j];
                a0 = fma2(hv0.x, Wp[2 * j], a0);
                a0 = fma2(hv0.y, Wp[2 * j + 1], a0);
                a1 = fma2(hv1.x, Wp[2 * j], a1);
                a1 = fma2(hv1.y, Wp[2 * j + 1], a1);
            }
            float2 u0 = unpack2(a0);
            float2 u1 = unpack2(a1);
            float v0 = u0.x + u0.y + p0;
            float v1 = u1.x + u1.y + p1;
            gact[0][g] = is_tanh_gate ? tanhf_(v0) : sigf(v0);
            gact[1][g] = is_tanh_gate ? tanhf_(v1) : sigf(v1);
            pre0 += G4;
            pre1 += G4;
        }
        __syncthreads();
        if (tid < 200) {
            float iv = gact[pr][pj];
            float fv = gact[pr][pj + 100];
            float gv = gact[pr][pj + 200];
            float ov = gact[pr][pj + 300];
            c = fv * c + iv * gv;
            hloc = ov * tanhf_(c);
            h_sh[pr][pj] = hloc;
        }
        __syncthreads();
    }

    if (tid < 200) g_hfinal[(r0 + pr) * HID + pj] = hloc;
}

// ================= K3: head  logits = (h@Wo^T + bo)@Wc^T + bc ====================
__global__ void head_kernel(const float* __restrict__ Wo, const float* __restrict__ bo,
                            const float* __restrict__ Wc, const float* __restrict__ bc,
                            float* __restrict__ out) {
    __shared__ float h[HID];
    __shared__ float emb[64];
    int b = blockIdx.x, tid = threadIdx.x;
    if (tid < HID) h[tid] = g_hfinal[b * HID + tid];
    __syncthreads();
    if (tid < 64) {
        float s = bo[tid];
#pragma unroll 4
        for (int j = 0; j < HID; j++) s += h[j] * Wo[tid * HID + j];
        emb[tid] = s;
    }
    __syncthreads();
    if (tid < 10) {
        float s = bc[tid];
#pragma unroll
        for (int e = 0; e < 64; e++) s += emb[e] * Wc[tid * 64 + e];
        out[b * 10 + tid] = s;
    }
}

// ================= launch ========================================================
extern "C" void kernel_launch(void* const* d_in, const int* in_sizes, int n_in,
                              void* d_out, int out_size) {
    const float* x    = (const float*)d_in[0];
    const float* Wih0 = (const float*)d_in[1];
    const float* Whh0 = (const float*)d_in[2];
    const float* bih0 = (const float*)d_in[3];
    const float* bhh0 = (const float*)d_in[4];
    // layers 1/2 (d_in[5..12]) are dead code in the reference
    const float* Wo = (const float*)d_in[13];
    const float* bo = (const float*)d_in[14];
    const float* Wc = (const float*)d_in[15];
    const float* bc = (const float*)d_in[16];
    float* out = (float*)d_out;

    prep_kernel<<<200, 256>>>(Wih0, bih0, bhh0);
    transpose_x_kernel<<<dim3(MTOT / 32, IND / 32), dim3(32, 8)>>>(x);
    gemm_pre_kernel<<<dim3(MTOT / 64, 4), 416>>>();
    lstm_kernel<<<128, 416>>>(Whh0);
    head_kernel<<<BB, 128>>>(Wo, bo, Wc, bc, out);
}

// round 2
// speedup vs baseline: 1.0343x; 1.0343x over previous
#include <cuda_runtime.h>
#include <cuda_bf16.h>

// Problem constants
#define BB   256
#define TT   512
#define IND  128
#define HID  100
#define G4   400          // 4*HID
#define MTOT (BB*TT)      // 131072

// ---------------- device scratch (static globals; no runtime alloc) -------------
__device__ float g_xT[IND * MTOT];          // [k][m]  transposed input (67 MB)
__device__ float g_WihT[IND * G4];          // [k][g]
__device__ float g_bias[G4];                // bih + bhh
__device__ float g_pre[(MTOT + 2) * G4];    // [m][g] input projection (+2 rows pad
                                            //  for the depth-2 prefetch tail)
__device__ float g_hfinal[BB * HID];        // layer-0 final hidden state

// ---------------- f32x2 packed helpers (Blackwell) ------------------------------
__device__ __forceinline__ unsigned long long fma2(unsigned long long a,
                                                   unsigned long long b,
                                                   unsigned long long c) {
    unsigned long long d;
    asm("fma.rn.f32x2 %0, %1, %2, %3;" : "=l"(d) : "l"(a), "l"(b), "l"(c));
    return d;
}
__device__ __forceinline__ unsigned long long pack2(float lo, float hi) {
    unsigned long long d;
    asm("mov.b64 %0, {%1, %2};" : "=l"(d) : "f"(lo), "f"(hi));
    return d;
}
__device__ __forceinline__ float2 unpack2(unsigned long long v) {
    float lo, hi;
    asm("mov.b64 {%0, %1}, %2;" : "=f"(lo), "=f"(hi) : "l"(v));
    return make_float2(lo, hi);
}

// ---------------- accurate-enough fast activations -------------------------------
__device__ __forceinline__ float sigf(float x) {
    float e = __expf(-fabsf(x));            // (0,1]
    float r = __fdividef(1.f, 1.f + e);     // sigma(|x|)
    return (x >= 0.f) ? r : 1.f - r;
}
__device__ __forceinline__ float tanhf_(float x) {
    float e = __expf(-2.f * fabsf(x));      // (0,1]
    float r = __fdividef(1.f - e, 1.f + e); // tanh(|x|)
    return (x >= 0.f) ? r : -r;
}

// ================= K-prep: WihT + fused bias =====================================
__global__ void prep_kernel(const float* __restrict__ Wih,
                            const float* __restrict__ bih,
                            const float* __restrict__ bhh) {
    int idx = blockIdx.x * 256 + threadIdx.x;
    if (idx < G4 * IND) {
        int g = idx / IND, k = idx - g * IND;
        g_WihT[k * G4 + g] = Wih[idx];
    }
    if (idx < G4) g_bias[idx] = bih[idx] + bhh[idx];
}

// ================= K0: transpose x [M,128] -> xT [128,M] =========================
__global__ void transpose_x_kernel(const float* __restrict__ x) {
    __shared__ float tile[32][33];
    int m0 = blockIdx.x * 32;
    int k0 = blockIdx.y * 32;
    int tx = threadIdx.x, ty = threadIdx.y;     // block (32,8)
#pragma unroll
    for (int j = 0; j < 32; j += 8)
        tile[ty + j][tx] = x[(m0 + ty + j) * IND + k0 + tx];
    __syncthreads();
#pragma unroll
    for (int j = 0; j < 32; j += 8)
        g_xT[(k0 + ty + j) * MTOT + m0 + tx] = tile[tx][ty + j];
}

// ================= K1: pre = x @ WihT + bias  (f32x2 GEMM) =======================
__global__ void __launch_bounds__(416, 2) gemm_pre_kernel() {
    __shared__ float xs[64 * 68];    // [k][row]
    __shared__ float ws[64 * 108];   // [k][gate]

    int tid = threadIdx.x;
    int m0 = blockIdx.x * 64;
    int g0 = blockIdx.y * 100;
    int ty = tid & 15;
    int tx = tid >> 4;

    unsigned long long acc[4][2];
#pragma unroll
    for (int r = 0; r < 4; r++) { acc[r][0] = 0ULL; acc[r][1] = 0ULL; }

    for (int kk = 0; kk < IND; kk += 64) {
        __syncthreads();
        for (int idx = tid; idx < 64 * 16; idx += 416) {
            int k = idx >> 4, i4 = idx & 15;
            float4 v = *(const float4*)&g_xT[(kk + k) * MTOT + m0 + 4 * i4];
            *(float4*)&xs[k * 68 + 4 * i4] = v;
        }
        for (int idx = tid; idx < 64 * 25; idx += 416) {
            int k = idx / 25, g4i = idx - 25 * k;
            float4 v = *(const float4*)&g_WihT[(kk + k) * G4 + g0 + 4 * g4i];
            *(float4*)&ws[k * 108 + 4 * g4i] = v;
        }
        __syncthreads();

        if (tx < 25) {
#pragma unroll 16
            for (int k = 0; k < 64; k++) {
                float4 xv = *(const float4*)&xs[k * 68 + 4 * ty];
                ulonglong2 wv = *(const ulonglong2*)&ws[k * 108 + 4 * tx];
                unsigned long long d0 = pack2(xv.x, xv.x);
                unsigned long long d1 = pack2(xv.y, xv.y);
                unsigned long long d2 = pack2(xv.z, xv.z);
                unsigned long long d3 = pack2(xv.w, xv.w);
                acc[0][0] = fma2(d0, wv.x, acc[0][0]);
                acc[0][1] = fma2(d0, wv.y, acc[0][1]);
                acc[1][0] = fma2(d1, wv.x, acc[1][0]);
                acc[1][1] = fma2(d1, wv.y, acc[1][1]);
                acc[2][0] = fma2(d2, wv.x, acc[2][0]);
                acc[2][1] = fma2(d2, wv.y, acc[2][1]);
                acc[3][0] = fma2(d3, wv.x, acc[3][0]);
                acc[3][1] = fma2(d3, wv.y, acc[3][1]);
            }
        }
    }

    if (tx < 25) {
        float b0 = g_bias[g0 + 4 * tx + 0];
        float b1 = g_bias[g0 + 4 * tx + 1];
        float b2 = g_bias[g0 + 4 * tx + 2];
        float b3 = g_bias[g0 + 4 * tx + 3];
#pragma unroll
        for (int r = 0; r < 4; r++) {
            float2 e0 = unpack2(acc[r][0]);
            float2 e1 = unpack2(acc[r][1]);
            float4 o = make_float4(e0.x + b0, e0.y + b1, e1.x + b2, e1.y + b3);
            *(float4*)&g_pre[(m0 + 4 * ty + r) * G4 + g0 + 4 * tx] = o;
        }
    }
}

// ================= K2: LSTM layer-0 recurrence ===================================
// 128 blocks, each owns 2 batch rows for all 512 steps.
// NEW: depth-2 software prefetch of the per-step `pre` rows. The loads for step
// t+2 issue before anything else in step t's phase-1, giving ~2 step-times of
// latency cover for the DRAM access (previously MLP=1, fully exposed).
__global__ void __launch_bounds__(416, 1) lstm_kernel(const float* __restrict__ Whh) {
    __shared__ float h_sh[2][112];
    __shared__ float gact[2][G4];

    int tid = threadIdx.x;
    int bid = blockIdx.x;
    int r0 = bid * 2;
    int g = tid;

    unsigned long long Wp[50];
    if (tid < G4) {
#pragma unroll
        for (int j = 0; j < 50; j++)
            Wp[j] = pack2(Whh[g * HID + 2 * j], Whh[g * HID + 2 * j + 1]);
    }
    if (tid < 112) { h_sh[0][tid] = 0.f; h_sh[1][tid] = 0.f; }

    float c = 0.f, hloc = 0.f;
    int pr = tid / 100;
    int pj = tid - pr * 100;

    const float* pre0 = g_pre + (r0 * TT) * G4 + g;
    const float* pre1 = pre0 + TT * G4;
    bool is_tanh_gate = (g >= 200 && g < 300);

    // depth-2 prefetch ring
    float pf0_a = 0.f, pf1_a = 0.f, pf0_b = 0.f, pf1_b = 0.f;
    if (tid < G4) {
        pf0_a = __ldg(pre0); pf1_a = __ldg(pre1); pre0 += G4; pre1 += G4;
        pf0_b = __ldg(pre0); pf1_b = __ldg(pre1); pre0 += G4; pre1 += G4;
    }

    __syncthreads();

#pragma unroll 2
    for (int t = 0; t < TT; t++) {
        int s = t & 1;   // compile-time after 2x unroll
        if (tid < G4) {
            float pc0, pc1;
            if (s == 0) {
                pc0 = pf0_a; pc1 = pf1_a;
                // prefetch t+2 (pad rows make the tail reads safe)
                pf0_a = __ldg(pre0); pf1_a = __ldg(pre1);
            } else {
                pc0 = pf0_b; pc1 = pf1_b;
                pf0_b = __ldg(pre0); pf1_b = __ldg(pre1);
            }
            pre0 += G4; pre1 += G4;

            unsigned long long a0 = 0ULL, a1 = 0ULL;
            const ulonglong2* h0p = (const ulonglong2*)&h_sh[0][0];
            const ulonglong2* h1p = (const ulonglong2*)&h_sh[1][0];
#pragma unroll
            for (int j = 0; j < 25; j++) {
                ulonglong2 hv0 = h0p[j];
                ulonglong2 hv1 = h1p[j];
                a0 = fma2(hv0.x, Wp[2 * j], a0);
                a0 = fma2(hv0.y, Wp[2 * j + 1], a0);
                a1 = fma2(hv1.x, Wp[2 * j], a1);
                a1 = fma2(hv1.y, Wp[2 * j + 1], a1);
            }
            float2 u0 = unpack2(a0);
            float2 u1 = unpack2(a1);
            float v0 = u0.x + u0.y + pc0;
            float v1 = u1.x + u1.y + pc1;
            gact[0][g] = is_tanh_gate ? tanhf_(v0) : sigf(v0);
            gact[1][g] = is_tanh_gate ? tanhf_(v1) : sigf(v1);
        }
        __syncthreads();
        if (tid < 200) {
            float iv = gact[pr][pj];
            float fv = gact[pr][pj + 100];
            float gv = gact[pr][pj + 200];
            float ov = gact[pr][pj + 300];
            c = fv * c + iv * gv;
            hloc = ov * tanhf_(c);
            h_sh[pr][pj] = hloc;
        }
        __syncthreads();
    }

    if (tid < 200) g_hfinal[(r0 + pr) * HID + pj] = hloc;
}

// ================= K3: head  logits = (h@Wo^T + bo)@Wc^T + bc ====================
__global__ void head_kernel(const float* __restrict__ Wo, const float* __restrict__ bo,
                            const float* __restrict__ Wc, const float* __restrict__ bc,
                            float* __restrict__ out) {
    __shared__ float h[HID];
    __shared__ float emb[64];
    int b = blockIdx.x, tid = threadIdx.x;
    if (tid < HID) h[tid] = g_hfinal[b * HID + tid];
    __syncthreads();
    if (tid < 64) {
        float s = bo[tid];
#pragma unroll 4
        for (int j = 0; j < HID; j++) s += h[j] * Wo[tid * HID + j];
        emb[tid] = s;
    }
    __syncthreads();
    if (tid < 10) {
        float s = bc[tid];
#pragma unroll
        for (int e = 0; e < 64; e++) s += emb[e] * Wc[tid * 64 + e];
        out[b * 10 + tid] = s;
    }
}

// ================= launch ========================================================
extern "C" void kernel_launch(void* const* d_in, const int* in_sizes, int n_in,
                              void* d_out, int out_size) {
    const float* x    = (const float*)d_in[0];
    const float* Wih0 = (const float*)d_in[1];
    const float* Whh0 = (const float*)d_in[2];
    const float* bih0 = (const float*)d_in[3];
    const float* bhh0 = (const float*)d_in[4];
    const float* Wo = (const float*)d_in[13];
    const float* bo = (const float*)d_in[14];
    const float* Wc = (const float*)d_in[15];
    const float* bc = (const float*)d_in[16];
    float* out = (float*)d_out;

    prep_kernel<<<200, 256>>>(Wih0, bih0, bhh0);
    transpose_x_kernel<<<dim3(MTOT / 32, IND / 32), dim3(32, 8)>>>(x);
    gemm_pre_kernel<<<dim3(MTOT / 64, 4), 416>>>();
    lstm_kernel<<<128, 416>>>(Whh0);
    head_kernel<<<BB, 128>>>(Wo, bo, Wc, bc, out);
}

// round 7
// speedup vs baseline: 1.1615x; 1.1230x over previous
#include <cuda_runtime.h>
#include <cuda_bf16.h>

// Problem constants
#define BB   256
#define TT   512
#define IND  128
#define HID  100
#define G4   400          // 4*HID
#define MTOT (BB*TT)      // 131072

// ---------------- device scratch (static globals; no runtime alloc) -------------
__device__ float g_WihT[IND * G4];          // [k][g]
__device__ float g_bias[G4];                // bih + bhh
__device__ float g_pre[(MTOT + 2) * G4];    // [m][g] input projection (+2 rows pad)
__device__ float g_hfinal[BB * HID];        // layer-0 final hidden state

// ---------------- f32x2 packed helpers (Blackwell) ------------------------------
__device__ __forceinline__ unsigned long long fma2(unsigned long long a,
                                                   unsigned long long b,
                                                   unsigned long long c) {
    unsigned long long d;
    asm("fma.rn.f32x2 %0, %1, %2, %3;" : "=l"(d) : "l"(a), "l"(b), "l"(c));
    return d;
}
__device__ __forceinline__ unsigned long long pack2(float lo, float hi) {
    unsigned long long d;
    asm("mov.b64 %0, {%1, %2};" : "=l"(d) : "f"(lo), "f"(hi));
    return d;
}
__device__ __forceinline__ float2 unpack2(unsigned long long v) {
    float lo, hi;
    asm("mov.b64 {%0, %1}, %2;" : "=f"(lo), "=f"(hi) : "l"(v));
    return make_float2(lo, hi);
}

// ---------------- accurate-enough fast activations -------------------------------
__device__ __forceinline__ float sigf(float x) {
    float e = __expf(-fabsf(x));            // (0,1]
    float r = __fdividef(1.f, 1.f + e);     // sigma(|x|)
    return (x >= 0.f) ? r : 1.f - r;
}
__device__ __forceinline__ float tanhf_(float x) {
    float e = __expf(-2.f * fabsf(x));      // (0,1]
    float r = __fdividef(1.f - e, 1.f + e); // tanh(|x|)
    return (x >= 0.f) ? r : -r;
}

// ================= K-prep: WihT + fused bias =====================================
__global__ void prep_kernel(const float* __restrict__ Wih,
                            const float* __restrict__ bih,
                            const float* __restrict__ bhh) {
    int idx = blockIdx.x * 256 + threadIdx.x;
    if (idx < G4 * IND) {
        int g = idx / IND, k = idx - g * IND;
        g_WihT[k * G4 + g] = Wih[idx];
    }
    if (idx < G4) g_bias[idx] = bih[idx] + bhh[idx];
}

// ================= K1: pre = x @ WihT + bias  (f32x2 GEMM) =======================
// Stages x directly from its native [M,128] layout (in-smem transpose).
__global__ void __launch_bounds__(416, 2) gemm_pre_kernel(const float* __restrict__ x) {
    __shared__ float xs[64 * 68];    // [k][row]
    __shared__ float ws[64 * 108];   // [k][gate]

    int tid = threadIdx.x;
    int m0 = blockIdx.x * 64;
    int g0 = blockIdx.y * 100;
    int ty = tid & 15;
    int tx = tid >> 4;

    unsigned long long acc[4][2];
#pragma unroll
    for (int r = 0; r < 4; r++) { acc[r][0] = 0ULL; acc[r][1] = 0ULL; }

    for (int kk = 0; kk < IND; kk += 64) {
        __syncthreads();
        // stage x tile 64 rows x 64 k with transpose into [k][row]
        for (int idx = tid; idx < 64 * 16; idx += 416) {
            int r = idx >> 4, c4 = idx & 15;
            float4 v = *(const float4*)&x[(m0 + r) * IND + kk + 4 * c4];
            xs[(4 * c4 + 0) * 68 + r] = v.x;
            xs[(4 * c4 + 1) * 68 + r] = v.y;
            xs[(4 * c4 + 2) * 68 + r] = v.z;
            xs[(4 * c4 + 3) * 68 + r] = v.w;
        }
        for (int idx = tid; idx < 64 * 25; idx += 416) {
            int k = idx / 25, g4i = idx - 25 * k;
            float4 v = *(const float4*)&g_WihT[(kk + k) * G4 + g0 + 4 * g4i];
            *(float4*)&ws[k * 108 + 4 * g4i] = v;
        }
        __syncthreads();

        if (tx < 25) {
#pragma unroll 16
            for (int k = 0; k < 64; k++) {
                float4 xv = *(const float4*)&xs[k * 68 + 4 * ty];
                ulonglong2 wv = *(const ulonglong2*)&ws[k * 108 + 4 * tx];
                unsigned long long d0 = pack2(xv.x, xv.x);
                unsigned long long d1 = pack2(xv.y, xv.y);
                unsigned long long d2 = pack2(xv.z, xv.z);
                unsigned long long d3 = pack2(xv.w, xv.w);
                acc[0][0] = fma2(d0, wv.x, acc[0][0]);
                acc[0][1] = fma2(d0, wv.y, acc[0][1]);
                acc[1][0] = fma2(d1, wv.x, acc[1][0]);
                acc[1][1] = fma2(d1, wv.y, acc[1][1]);
                acc[2][0] = fma2(d2, wv.x, acc[2][0]);
                acc[2][1] = fma2(d2, wv.y, acc[2][1]);
                acc[3][0] = fma2(d3, wv.x, acc[3][0]);
                acc[3][1] = fma2(d3, wv.y, acc[3][1]);
            }
        }
    }

    if (tx < 25) {
        float b0 = g_bias[g0 + 4 * tx + 0];
        float b1 = g_bias[g0 + 4 * tx + 1];
        float b2 = g_bias[g0 + 4 * tx + 2];
        float b3 = g_bias[g0 + 4 * tx + 3];
#pragma unroll
        for (int r = 0; r < 4; r++) {
            float2 e0 = unpack2(acc[r][0]);
            float2 e1 = unpack2(acc[r][1]);
            float4 o = make_float4(e0.x + b0, e0.y + b1, e1.x + b2, e1.y + b3);
            *(float4*)&g_pre[(m0 + 4 * ty + r) * G4 + g0 + 4 * tx] = o;
        }
    }
}

// ================= K2: LSTM layer-0 recurrence (split-K, 800 threads) ============
// 128 blocks, each owns 2 batch rows. Thread = (gate q = tid>>1, k-half = tid&1).
// Each thread holds HALF of Whh's row (52 packed regs, k padded 100->104 with
// zeros). NEW vs r2: each row's accumulator is split into two independent
// 13-deep fma2 chains (4 chains total), halving the per-step dependent-latency.
// Halves combine with one shfl_xor against the adjacent lane.
__global__ void __launch_bounds__(800, 1) lstm_kernel(const float* __restrict__ Whh) {
    __shared__ float h_sh[2][112];     // [100..112) stay 0 -> zero-padded k-slice
    __shared__ float gact[2][G4];

    int tid = threadIdx.x;
    int bid = blockIdx.x;
    int r0 = bid * 2;
    int q = tid >> 1;          // gate index 0..399
    int half = tid & 1;        // k-half: [0,52) or [52,104)

    // Whh half-row in packed registers (zero-pad k >= 100)
    unsigned long long Wp[26];
#pragma unroll
    for (int j = 0; j < 26; j++) {
        int k = half * 52 + 2 * j;
        float lo = (k < HID)     ? Whh[q * HID + k]     : 0.f;
        float hi = (k + 1 < HID) ? Whh[q * HID + k + 1] : 0.f;
        Wp[j] = pack2(lo, hi);
    }
    if (tid < 224) ((float*)h_sh)[tid] = 0.f;

    // phase-2 state: thread tid<200 owns (row pr, unit pj)
    float c = 0.f, hloc = 0.f;
    int pr = tid / 100;
    int pj = tid - pr * 100;

    // this thread fetches pre for row `half`, gate q
    const float* prep = g_pre + ((size_t)(r0 + half) * TT) * G4 + q;
    bool is_tanh_gate = (q >= 200 && q < 300);

    // depth-2 prefetch ring
    float pfa = __ldg(prep); prep += G4;
    float pfb = __ldg(prep); prep += G4;

    __syncthreads();

#pragma unroll 2
    for (int t = 0; t < TT; t++) {
        float pc;
        if ((t & 1) == 0) { pc = pfa; pfa = __ldg(prep); }
        else              { pc = pfb; pfb = __ldg(prep); }
        prep += G4;

        // 4 independent 13-deep chains
        unsigned long long a0x = 0ULL, a0y = 0ULL, a1x = 0ULL, a1y = 0ULL;
        const ulonglong2* hp0 = (const ulonglong2*)&h_sh[0][half * 52];
        const ulonglong2* hp1 = (const ulonglong2*)&h_sh[1][half * 52];
#pragma unroll
        for (int j = 0; j < 13; j++) {
            ulonglong2 hv0 = hp0[j];
            ulonglong2 hv1 = hp1[j];
            a0x = fma2(hv0.x, Wp[2 * j], a0x);
            a0y = fma2(hv0.y, Wp[2 * j + 1], a0y);
            a1x = fma2(hv1.x, Wp[2 * j], a1x);
            a1y = fma2(hv1.y, Wp[2 * j + 1], a1y);
        }
        float2 u0x = unpack2(a0x), u0y = unpack2(a0y);
        float2 u1x = unpack2(a1x), u1y = unpack2(a1y);
        float s0 = (u0x.x + u0x.y) + (u0y.x + u0y.y);
        float s1 = (u1x.x + u1x.y) + (u1y.x + u1y.y);
        s0 += __shfl_xor_sync(0xFFFFFFFFu, s0, 1);
        s1 += __shfl_xor_sync(0xFFFFFFFFu, s1, 1);
        float v = (half ? s1 : s0) + pc;
        gact[half][q] = is_tanh_gate ? tanhf_(v) : sigf(v);

        __syncthreads();
        if (tid < 200) {
            float iv = gact[pr][pj];
            float fv = gact[pr][pj + 100];
            float gv = gact[pr][pj + 200];
            float ov = gact[pr][pj + 300];
            c = fv * c + iv * gv;
            hloc = ov * tanhf_(c);
            h_sh[pr][pj] = hloc;
        }
        __syncthreads();
    }

    if (tid < 200) g_hfinal[(r0 + pr) * HID + pj] = hloc;
}

// ================= K3: head  logits = (h@Wo^T + bo)@Wc^T + bc ====================
__global__ void head_kernel(const float* __restrict__ Wo, const float* __restrict__ bo,
                            const float* __restrict__ Wc, const float* __restrict__ bc,
                            float* __restrict__ out) {
    __shared__ float h[HID];
    __shared__ float emb[64];
    int b = blockIdx.x, tid = threadIdx.x;
    if (tid < HID) h[tid] = g_hfinal[b * HID + tid];
    __syncthreads();
    if (tid < 64) {
        float s = bo[tid];
#pragma unroll 4
        for (int j = 0; j < HID; j++) s += h[j] * Wo[tid * HID + j];
        emb[tid] = s;
    }
    __syncthreads();
    if (tid < 10) {
        float s = bc[tid];
#pragma unroll
        for (int e = 0; e < 64; e++) s += emb[e] * Wc[tid * 64 + e];
        out[b * 10 + tid] = s;
    }
}

// ================= launch ========================================================
extern "C" void kernel_launch(void* const* d_in, const int* in_sizes, int n_in,
                              void* d_out, int out_size) {
    const float* x    = (const float*)d_in[0];
    const float* Wih0 = (const float*)d_in[1];
    const float* Whh0 = (const float*)d_in[2];
    const float* bih0 = (const float*)d_in[3];
    const float* bhh0 = (const float*)d_in[4];
    const float* Wo = (const float*)d_in[13];
    const float* bo = (const float*)d_in[14];
    const float* Wc = (const float*)d_in[15];
    const float* bc = (const float*)d_in[16];
    float* out = (float*)d_out;

    prep_kernel<<<200, 256>>>(Wih0, bih0, bhh0);
    gemm_pre_kernel<<<dim3(MTOT / 64, 4), 416>>>(x);
    lstm_kernel<<<128, 800>>>(Whh0);
    head_kernel<<<BB, 128>>>(Wo, bo, Wc, bc, out);
}